// round 15
// baseline (speedup 1.0000x reference)
#include <cuda_runtime.h>
#include <mma.h>
#include <cstdint>
#include <cstddef>

using namespace nvcuda;

#define SQ     2048
#define DMODEL 1024
#define NH     8
#define DK     128
#define DV     128
#define KCONV  4

// ---------------- scratch ----------------
#define NBIGF   (2097152)              // SQ*DMODEL
#define OFF_XQ   ((size_t)0  * NBIGF)
#define OFF_XK   ((size_t)1  * NBIGF)
#define OFF_XV   ((size_t)2  * NBIGF)
#define OFF_XVE  ((size_t)3  * NBIGF)
#define OFF_CQ   ((size_t)4  * NBIGF)
#define OFF_CK   ((size_t)5  * NBIGF)
#define OFF_CV   ((size_t)6  * NBIGF)
#define OFF_GPRE ((size_t)7  * NBIGF)
#define OFF_GOUT ((size_t)8  * NBIGF)
#define OFF_O    ((size_t)9  * NBIGF)
#define OFF_XR   ((size_t)10 * NBIGF)
#define OFF_VER  ((size_t)11 * NBIGF)
#define OFF_WQR  ((size_t)12 * NBIGF)
#define OFF_WKR  (OFF_WQR + (size_t)1048576)
#define OFF_WVR  (OFF_WKR + (size_t)1048576)
#define OFF_WOR  (OFF_WVR + (size_t)1048576)
#define OFF_WG1R (OFF_WOR + (size_t)1048576)
#define OFF_WG2R (OFF_WG1R + (size_t)131072)
#define OFF_F1   (OFF_WG2R + (size_t)131072)
#define OFF_G1   (OFF_F1 + (size_t)SQ*128)
#define OFF_BPRE (OFF_G1 + (size_t)SQ*128)
#define SCRATCH_FLOATS (OFF_BPRE + (size_t)SQ*NH)

__device__ float g_scratch[SCRATCH_FLOATS];

// ================= helpers =================
__device__ __forceinline__ uint32_t smem_u32(const void* p) {
    uint32_t a;
    asm("{ .reg .u64 t; cvta.to.shared.u64 t, %1; cvt.u32.u64 %0, t; }" : "=r"(a) : "l"(p));
    return a;
}
__device__ __forceinline__ void cp16(uint32_t saddr, const void* g) {
    asm volatile("cp.async.cg.shared.global [%0], [%1], 16;" :: "r"(saddr), "l"(g));
}
#define CP_COMMIT() asm volatile("cp.async.commit_group;" ::: "memory")

// ================= WMMA tf32 NT GEMM v2: 128x128 tile, BK=32, dynamic smem =================
// 2-stage cp.async pipeline. smem stride 36 floats per row (16B-aligned rows,
// 2-way-conflict fragment loads — same profile as BK=16/stride 20).
#define BK2       32
#define ST2       36                      // floats per smem row
#define TILE_F    (128 * ST2)             // floats per array per stage
#define GSMEM_V2  (4 * TILE_F * 4)        // bytes: 2 stages x (As+Bs)

__device__ __forceinline__ void gemm128_body(
    const float* __restrict__ A, const float* __restrict__ B,
    float* __restrict__ C, int N, int K, int rowBlk, int colBlk)
{
    extern __shared__ float dsm[];
    float* Asm = dsm;                  // [2][128][ST2]
    float* Bsm = dsm + 2 * TILE_F;     // [2][128][ST2]

    const int tid = threadIdx.x;
    const int wid = tid >> 5;
    const int wr = wid >> 1;           // 0..3
    const int wc = wid & 1;            // 0..1

    const int lr = tid >> 1;           // 0..127
    const int lc = (tid & 1) * 16;     // 0 or 16
    const float* gA = A + (size_t)(rowBlk + lr) * K + lc;
    const float* gB = B + (size_t)(colBlk + lr) * K + lc;
    const uint32_t sA = smem_u32(Asm) + (lr * ST2 + lc) * 4;
    const uint32_t sB = smem_u32(Bsm) + (lr * ST2 + lc) * 4;

    wmma::fragment<wmma::accumulator, 16, 16, 8, float> acc[2][4];
#pragma unroll
    for (int i = 0; i < 2; i++)
#pragma unroll
        for (int j = 0; j < 4; j++) wmma::fill_fragment(acc[i][j], 0.f);

    auto load_tile = [&](int k0, int st) {
        const uint32_t stoff = st * TILE_F * 4;
#pragma unroll
        for (int i = 0; i < 4; i++) {
            cp16(sA + stoff + i * 16, gA + k0 + i * 4);
            cp16(sB + stoff + i * 16, gB + k0 + i * 4);
        }
    };

    const int nk = K / BK2;
    load_tile(0, 0);
    CP_COMMIT();

    for (int i = 0; i < nk; i++) {
        const int st = i & 1;
        if (i + 1 < nk) {
            load_tile((i + 1) * BK2, st ^ 1);
            CP_COMMIT();
            asm volatile("cp.async.wait_group 1;" ::: "memory");
        } else {
            asm volatile("cp.async.wait_group 0;" ::: "memory");
        }
        __syncthreads();

        const float* Ab = Asm + st * TILE_F + (wr * 32) * ST2;
        const float* Bb = Bsm + st * TILE_F + (wc * 64) * ST2;
#pragma unroll
        for (int kk = 0; kk < BK2; kk += 8) {
            wmma::fragment<wmma::matrix_a, 16, 16, 8, wmma::precision::tf32, wmma::row_major> af[2];
            wmma::fragment<wmma::matrix_b, 16, 16, 8, wmma::precision::tf32, wmma::col_major> bf[4];
#pragma unroll
            for (int i2 = 0; i2 < 2; i2++)
                wmma::load_matrix_sync(af[i2], Ab + i2 * 16 * ST2 + kk, ST2);
#pragma unroll
            for (int j = 0; j < 4; j++)
                wmma::load_matrix_sync(bf[j], Bb + j * 16 * ST2 + kk, ST2);
#pragma unroll
            for (int i2 = 0; i2 < 2; i2++)
#pragma unroll
                for (int j = 0; j < 4; j++)
                    wmma::mma_sync(acc[i2][j], af[i2], bf[j], acc[i2][j]);
        }
        __syncthreads();
    }

#pragma unroll
    for (int i = 0; i < 2; i++)
#pragma unroll
        for (int j = 0; j < 4; j++)
            wmma::store_matrix_sync(
                C + (size_t)(rowBlk + wr * 32 + i * 16) * N + colBlk + wc * 64 + j * 16,
                acc[i][j], N, wmma::mem_row_major);
}

__global__ void __launch_bounds__(256) gemm_tf32(
    const float* __restrict__ A, const float* __restrict__ B,
    float* __restrict__ C, int M, int N, int K)
{
    gemm128_body(A, B, C, N, K, blockIdx.y * 128, blockIdx.x * 128);
}

struct Gemm4 { const float* A[4]; const float* B[4]; float* C[4]; };

__global__ void __launch_bounds__(256) gemm_tf32_b4(Gemm4 p, int N, int K)
{
    const int z = blockIdx.z;
    gemm128_body(p.A[z], p.B[z], p.C[z], N, K, blockIdx.y * 128, blockIdx.x * 128);
}

// ================= WMMA tf32 64x64-tile GEMM with tf32-rounded output =================
#define BK 16
#define LDS_PAD 4
#define LDS_STRIDE (BK + LDS_PAD)   // 20

__global__ void __launch_bounds__(128) gemm_tf32_64r(
    const float* __restrict__ A, const float* __restrict__ B,
    float* __restrict__ C, int M, int N, int K)
{
    __shared__ __align__(16) float As[2][64][LDS_STRIDE];
    __shared__ __align__(16) float Bs[2][64][LDS_STRIDE];

    const int tid = threadIdx.x;
    const int wid = tid >> 5;
    const int wr = wid >> 1;
    const int wc = wid & 1;
    const int rowBlk = blockIdx.y * 64;
    const int colBlk = blockIdx.x * 64;

    const int lr = tid >> 1;
    const int lc = (tid & 1) * 8;
    const float* gA = A + (size_t)(rowBlk + lr) * K + lc;
    const float* gB = B + (size_t)(colBlk + lr) * K + lc;

    wmma::fragment<wmma::accumulator, 16, 16, 8, float> acc[2][2];
#pragma unroll
    for (int i = 0; i < 2; i++)
#pragma unroll
        for (int j = 0; j < 2; j++) wmma::fill_fragment(acc[i][j], 0.f);

    auto load_tile = [&](int k0, int st) {
        cp16(smem_u32(&As[st][lr][lc]),     gA + k0);
        cp16(smem_u32(&As[st][lr][lc + 4]), gA + k0 + 4);
        cp16(smem_u32(&Bs[st][lr][lc]),     gB + k0);
        cp16(smem_u32(&Bs[st][lr][lc + 4]), gB + k0 + 4);
    };

    const int nk = K / BK;
    load_tile(0, 0);
    CP_COMMIT();

    for (int i = 0; i < nk; i++) {
        const int st = i & 1;
        if (i + 1 < nk) {
            load_tile((i + 1) * BK, st ^ 1);
            CP_COMMIT();
            asm volatile("cp.async.wait_group 1;" ::: "memory");
        } else {
            asm volatile("cp.async.wait_group 0;" ::: "memory");
        }
        __syncthreads();

#pragma unroll
        for (int kk = 0; kk < BK; kk += 8) {
            wmma::fragment<wmma::matrix_a, 16, 16, 8, wmma::precision::tf32, wmma::row_major> af[2];
            wmma::fragment<wmma::matrix_b, 16, 16, 8, wmma::precision::tf32, wmma::col_major> bf[2];
#pragma unroll
            for (int i2 = 0; i2 < 2; i2++)
                wmma::load_matrix_sync(af[i2], &As[st][wr * 32 + i2 * 16][kk], LDS_STRIDE);
#pragma unroll
            for (int j = 0; j < 2; j++)
                wmma::load_matrix_sync(bf[j], &Bs[st][wc * 32 + j * 16][kk], LDS_STRIDE);
#pragma unroll
            for (int i2 = 0; i2 < 2; i2++)
#pragma unroll
                for (int j = 0; j < 2; j++)
                    wmma::mma_sync(acc[i2][j], af[i2], bf[j], acc[i2][j]);
        }
        __syncthreads();
    }

#pragma unroll
    for (int i = 0; i < 2; i++)
#pragma unroll
        for (int j = 0; j < 2; j++) {
#pragma unroll
            for (int e = 0; e < acc[i][j].num_elements; e++) {
                uint32_t u;
                asm("cvt.rna.tf32.f32 %0, %1;" : "=r"(u) : "f"(acc[i][j].x[e]));
                acc[i][j].x[e] = __uint_as_float(u);
            }
            wmma::store_matrix_sync(
                C + (size_t)(rowBlk + wr * 32 + i * 16) * N + colBlk + wc * 32 + j * 16,
                acc[i][j], N, wmma::mem_row_major);
        }
}

// ================= fp32 SIMT GEMMs (accuracy-critical decay path) =================
__global__ void __launch_bounds__(256) sgemm_gate(
    const float* __restrict__ A, const float* __restrict__ B,
    float* __restrict__ C, int M, int N, int Ksz,
    const float* __restrict__ A_log, const float* __restrict__ dt_bias)
{
    __shared__ __align__(16) float As2[16][128];
    __shared__ __align__(16) float Bs2[16][128];

    const int tid = threadIdx.x;
    const int tx = tid & 15;
    const int ty = tid >> 4;
    const int rowC = blockIdx.y * 128 + ty * 8;
    const int colC = blockIdx.x * 128 + tx * 8;
    const int lrow = tid >> 2;
    const int lk   = (tid & 3) * 4;

    float acc[8][8];
#pragma unroll
    for (int i = 0; i < 8; i++)
#pragma unroll
        for (int j = 0; j < 8; j++) acc[i][j] = 0.f;

    for (int k0 = 0; k0 < Ksz; k0 += 16) {
#pragma unroll
        for (int rr = 0; rr < 2; rr++) {
            const int r = lrow + rr * 64;
            {
                const int grow = blockIdx.y * 128 + r;
                float4 av = make_float4(0.f, 0.f, 0.f, 0.f);
                if (grow < M)
                    av = *reinterpret_cast<const float4*>(A + (size_t)grow * Ksz + k0 + lk);
                As2[lk + 0][r] = av.x; As2[lk + 1][r] = av.y;
                As2[lk + 2][r] = av.z; As2[lk + 3][r] = av.w;
            }
            {
                const int gcol = blockIdx.x * 128 + r;
                float4 bv = make_float4(0.f, 0.f, 0.f, 0.f);
                if (gcol < N)
                    bv = *reinterpret_cast<const float4*>(B + (size_t)gcol * Ksz + k0 + lk);
                Bs2[lk + 0][r] = bv.x; Bs2[lk + 1][r] = bv.y;
                Bs2[lk + 2][r] = bv.z; Bs2[lk + 3][r] = bv.w;
            }
        }
        __syncthreads();
#pragma unroll
        for (int kk = 0; kk < 16; kk++) {
            float a[8], b[8];
            *reinterpret_cast<float4*>(a)     = *reinterpret_cast<const float4*>(&As2[kk][ty * 8]);
            *reinterpret_cast<float4*>(a + 4) = *reinterpret_cast<const float4*>(&As2[kk][ty * 8 + 4]);
            *reinterpret_cast<float4*>(b)     = *reinterpret_cast<const float4*>(&Bs2[kk][tx * 8]);
            *reinterpret_cast<float4*>(b + 4) = *reinterpret_cast<const float4*>(&Bs2[kk][tx * 8 + 4]);
#pragma unroll
            for (int i = 0; i < 8; i++)
#pragma unroll
                for (int j = 0; j < 8; j++)
                    acc[i][j] = fmaf(a[i], b[j], acc[i][j]);
        }
        __syncthreads();
    }
#pragma unroll
    for (int i = 0; i < 8; i++) {
        const int r = rowC + i;
        if (r >= M) continue;
#pragma unroll
        for (int j = 0; j < 8; j++) {
            const int c = colC + j;
            if (c < N) {
                float xv = acc[i][j] + dt_bias[c];
                float spv = fmaxf(xv, 0.f) + log1pf(expf(-fabsf(xv)));
                C[(size_t)r * N + c] = expf(-expf(A_log[c >> 7]) * spv);
            }
        }
    }
}

__global__ void __launch_bounds__(256) sgemm_nt_sk(
    const float* __restrict__ A, const float* __restrict__ B,
    float* __restrict__ C, int M, int Ksz)
{
    __shared__ __align__(16) float As3[16][32];
    __shared__ __align__(16) float Bs3[16][128];

    const int tid = threadIdx.x;
    const int tx = tid & 15;
    const int ty = tid >> 4;
    const int rowBlk = blockIdx.y * 32;

    const int arow = tid >> 3;
    const int ak   = (tid & 7) * 2;
    const int brow = tid >> 1;
    const int bk   = (tid & 1) * 8;

    float acc[2][8];
#pragma unroll
    for (int i = 0; i < 2; i++)
#pragma unroll
        for (int j = 0; j < 8; j++) acc[i][j] = 0.f;

    for (int k0 = 0; k0 < Ksz; k0 += 16) {
        {
            float2 av = *reinterpret_cast<const float2*>(A + (size_t)(rowBlk + arow) * Ksz + k0 + ak);
            As3[ak + 0][arow] = av.x; As3[ak + 1][arow] = av.y;
        }
        {
            float4 b0 = *reinterpret_cast<const float4*>(B + (size_t)brow * Ksz + k0 + bk);
            float4 b1 = *reinterpret_cast<const float4*>(B + (size_t)brow * Ksz + k0 + bk + 4);
            Bs3[bk + 0][brow] = b0.x; Bs3[bk + 1][brow] = b0.y;
            Bs3[bk + 2][brow] = b0.z; Bs3[bk + 3][brow] = b0.w;
            Bs3[bk + 4][brow] = b1.x; Bs3[bk + 5][brow] = b1.y;
            Bs3[bk + 6][brow] = b1.z; Bs3[bk + 7][brow] = b1.w;
        }
        __syncthreads();
#pragma unroll
        for (int kk = 0; kk < 16; kk++) {
            float a0 = As3[kk][ty * 2], a1 = As3[kk][ty * 2 + 1];
            float b[8];
            *reinterpret_cast<float4*>(b)     = *reinterpret_cast<const float4*>(&Bs3[kk][tx * 8]);
            *reinterpret_cast<float4*>(b + 4) = *reinterpret_cast<const float4*>(&Bs3[kk][tx * 8 + 4]);
#pragma unroll
            for (int j = 0; j < 8; j++) {
                acc[0][j] = fmaf(a0, b[j], acc[0][j]);
                acc[1][j] = fmaf(a1, b[j], acc[1][j]);
            }
        }
        __syncthreads();
    }
#pragma unroll
    for (int i = 0; i < 2; i++) {
        float* cp = C + (size_t)(rowBlk + ty * 2 + i) * 128 + tx * 8;
#pragma unroll
        for (int j = 0; j < 8; j++) cp[j] = acc[i][j];
    }
}

// ================= fused tf32 rounding =================
struct RoundPack {
    const float* src[8];
    float* dst[8];
    int n4[8];
};

__global__ void round_all_kernel(RoundPack p)
{
    const int r = blockIdx.y;
    const int i = blockIdx.x * blockDim.x + threadIdx.x;
    if (i >= p.n4[r]) return;
    float4 v = reinterpret_cast<const float4*>(p.src[r])[i];
    uint4 u;
    asm("cvt.rna.tf32.f32 %0, %1;" : "=r"(u.x) : "f"(v.x));
    asm("cvt.rna.tf32.f32 %0, %1;" : "=r"(u.y) : "f"(v.y));
    asm("cvt.rna.tf32.f32 %0, %1;" : "=r"(u.z) : "f"(v.z));
    asm("cvt.rna.tf32.f32 %0, %1;" : "=r"(u.w) : "f"(v.w));
    reinterpret_cast<uint4*>(p.dst[r])[i] = u;
}

// ================= fused conv+silu+l2norm for q/k =================
__global__ void __launch_bounds__(256) conv_l2_qk_kernel(
    const float* __restrict__ xq, const float* __restrict__ xk,
    const float* __restrict__ wqc, const float* __restrict__ wkc,
    float* __restrict__ cq, float* __restrict__ ck)
{
    const int s = blockIdx.x;
    const int tid = threadIdx.x;
    const int d = tid * 4;

    float wq[4][4], wk[4][4];
#pragma unroll
    for (int c = 0; c < 4; c++) {
        float4 a = *reinterpret_cast<const float4*>(wqc + (d + c) * 4);
        wq[c][0] = a.x; wq[c][1] = a.y; wq[c][2] = a.z; wq[c][3] = a.w;
        float4 b = *reinterpret_cast<const float4*>(wkc + (d + c) * 4);
        wk[c][0] = b.x; wk[c][1] = b.y; wk[c][2] = b.z; wk[c][3] = b.w;
    }

    float aq[4] = {0.f, 0.f, 0.f, 0.f};
    float ak[4] = {0.f, 0.f, 0.f, 0.f};
#pragma unroll
    for (int i = 0; i < KCONV; i++) {
        const int sp = s - (KCONV - 1) + i;
        if (sp >= 0) {
            float4 xv = *reinterpret_cast<const float4*>(xq + (size_t)sp * DMODEL + d);
            aq[0] = fmaf(xv.x, wq[0][i], aq[0]);
            aq[1] = fmaf(xv.y, wq[1][i], aq[1]);
            aq[2] = fmaf(xv.z, wq[2][i], aq[2]);
            aq[3] = fmaf(xv.w, wq[3][i], aq[3]);
            float4 kv = *reinterpret_cast<const float4*>(xk + (size_t)sp * DMODEL + d);
            ak[0] = fmaf(kv.x, wk[0][i], ak[0]);
            ak[1] = fmaf(kv.y, wk[1][i], ak[1]);
            ak[2] = fmaf(kv.z, wk[2][i], ak[2]);
            ak[3] = fmaf(kv.w, wk[3][i], ak[3]);
        }
    }

    float ssq = 0.f, ssk = 0.f;
#pragma unroll
    for (int c = 0; c < 4; c++) {
        aq[c] = aq[c] / (1.f + expf(-aq[c]));
        ak[c] = ak[c] / (1.f + expf(-ak[c]));
        ssq = fmaf(aq[c], aq[c], ssq);
        ssk = fmaf(ak[c], ak[c], ssk);
    }
#pragma unroll
    for (int o = 16; o; o >>= 1) {
        ssq += __shfl_xor_sync(0xffffffffu, ssq, o);
        ssk += __shfl_xor_sync(0xffffffffu, ssk, o);
    }
    const float rq = rsqrtf(ssq + 1e-6f) * 0.08838834764831845f;
    const float rk = rsqrtf(ssk + 1e-6f);

    float4 oq = make_float4(aq[0] * rq, aq[1] * rq, aq[2] * rq, aq[3] * rq);
    float4 ok = make_float4(ak[0] * rk, ak[1] * rk, ak[2] * rk, ak[3] * rk);
    *reinterpret_cast<float4*>(cq + (size_t)s * DMODEL + d) = oq;
    *reinterpret_cast<float4*>(ck + (size_t)s * DMODEL + d) = ok;
}

__global__ void convmix_silu_kernel(const float* __restrict__ xv,
                                    const float* __restrict__ xve,
                                    const float* __restrict__ w,
                                    const float* __restrict__ lam,
                                    float* __restrict__ out, int n)
{
    int idx = blockIdx.x * blockDim.x + threadIdx.x;
    if (idx >= n) return;
    int s = idx >> 10;
    int d = idx & 1023;
    float a = 0.f, b = 0.f;
#pragma unroll
    for (int i = 0; i < KCONV; i++) {
        int sp = s - (KCONV - 1) + i;
        if (sp >= 0) {
            const float wt = w[d * KCONV + i];
            a = fmaf(xv[(size_t)sp * DMODEL + d], wt, a);
            b = fmaf(xve[(size_t)sp * DMODEL + d], wt, b);
        }
    }
    const float sa = a / (1.f + expf(-a));
    const float sb = b / (1.f + expf(-b));
    out[idx] = lam[0] * sa + lam[1] * sb;
}

__global__ void __launch_bounds__(256) beta_kernel(const float* __restrict__ x,
                                                   const float* __restrict__ Wb,
                                                   float* __restrict__ out)
{
    const int s = blockIdx.x;
    const int h = threadIdx.x >> 5;
    const int l = threadIdx.x & 31;
    float acc = 0.f;
#pragma unroll
    for (int j = 0; j < 8; j++) {
        float4 xv = *reinterpret_cast<const float4*>(x + (size_t)s * DMODEL + j * 128 + l * 4);
        float4 wv = *reinterpret_cast<const float4*>(Wb + (size_t)h * DMODEL + j * 128 + l * 4);
        acc = fmaf(xv.x, wv.x, acc); acc = fmaf(xv.y, wv.y, acc);
        acc = fmaf(xv.z, wv.z, acc); acc = fmaf(xv.w, wv.w, acc);
    }
#pragma unroll
    for (int o = 16; o; o >>= 1) acc += __shfl_xor_sync(0xffffffffu, acc, o);
    if (l == 0) out[(size_t)s * NH + h] = 1.f / (1.f + expf(-acc));
}

// ================= KDA scan (pipelined, merged shfl tree) =================
__global__ void __launch_bounds__(128) kda_scan_kernel(
    const float* __restrict__ qn, const float* __restrict__ kn,
    const float* __restrict__ v,  const float* __restrict__ ed,
    const float* __restrict__ beta, float* __restrict__ o)
{
    const int h  = blockIdx.x >> 4;
    const int cg = blockIdx.x & 15;
    const int w  = threadIdx.x >> 5;
    const int l  = threadIdx.x & 31;
    const int cw = l >> 4;
    const int rg = l & 15;
    const int col = cg * 8 + w * 2 + cw;
    const int r0  = rg * 8;

    float S[8];
#pragma unroll
    for (int i = 0; i < 8; i++) S[i] = 0.f;

    auto loadstep = [&](int t, float* e, float* k, float* q, float& vv, float& bb) {
        const int tt = t < SQ ? t : SQ - 1;
        const size_t base = ((size_t)tt * NH + h) * DK;
        float4 x0 = __ldg(reinterpret_cast<const float4*>(ed + base + r0));
        float4 x1 = __ldg(reinterpret_cast<const float4*>(ed + base + r0 + 4));
        e[0] = x0.x; e[1] = x0.y; e[2] = x0.z; e[3] = x0.w;
        e[4] = x1.x; e[5] = x1.y; e[6] = x1.z; e[7] = x1.w;
        x0 = __ldg(reinterpret_cast<const float4*>(kn + base + r0));
        x1 = __ldg(reinterpret_cast<const float4*>(kn + base + r0 + 4));
        k[0] = x0.x; k[1] = x0.y; k[2] = x0.z; k[3] = x0.w;
        k[4] = x1.x; k[5] = x1.y; k[6] = x1.z; k[7] = x1.w;
        x0 = __ldg(reinterpret_cast<const float4*>(qn + base + r0));
        x1 = __ldg(reinterpret_cast<const float4*>(qn + base + r0 + 4));
        q[0] = x0.x; q[1] = x0.y; q[2] = x0.z; q[3] = x0.w;
        q[4] = x1.x; q[5] = x1.y; q[6] = x1.z; q[7] = x1.w;
        vv = __ldg(v + ((size_t)tt * NH + h) * DV + col);
        bb = __ldg(beta + (size_t)tt * NH + h);
    };

    auto step = [&](int t, const float* e, const float* k, const float* q,
                    float vc, float bt) {
        float eS[8];
#pragma unroll
        for (int i = 0; i < 8; i++) eS[i] = e[i] * S[i];

        float a0 = 0.f, a1 = 0.f, a2 = 0.f, a3 = 0.f;
        float c0 = 0.f, c1 = 0.f, c2 = 0.f, c3 = 0.f;
        float d0 = 0.f, d1 = 0.f, d2 = 0.f, d3 = 0.f;
#pragma unroll
        for (int i = 0; i < 8; i += 4) {
            a0 = fmaf(k[i + 0], eS[i + 0], a0);
            a1 = fmaf(k[i + 1], eS[i + 1], a1);
            a2 = fmaf(k[i + 2], eS[i + 2], a2);
            a3 = fmaf(k[i + 3], eS[i + 3], a3);
            c0 = fmaf(q[i + 0], eS[i + 0], c0);
            c1 = fmaf(q[i + 1], eS[i + 1], c1);
            c2 = fmaf(q[i + 2], eS[i + 2], c2);
            c3 = fmaf(q[i + 3], eS[i + 3], c3);
            d0 = fmaf(q[i + 0], k[i + 0], d0);
            d1 = fmaf(q[i + 1], k[i + 1], d1);
            d2 = fmaf(q[i + 2], k[i + 2], d2);
            d3 = fmaf(q[i + 3], k[i + 3], d3);
        }
        float a = (a0 + a1) + (a2 + a3);
        float c = (c0 + c1) + (c2 + c3);
        float d = (d0 + d1) + (d2 + d3);
#pragma unroll
        for (int off = 1; off < 16; off <<= 1) {
            a += __shfl_xor_sync(0xffffffffu, a, off);
            c += __shfl_xor_sync(0xffffffffu, c, off);
            d += __shfl_xor_sync(0xffffffffu, d, off);
        }

        const float vnew = (vc - a) * bt;
#pragma unroll
        for (int i = 0; i < 8; i++) S[i] = fmaf(k[i], vnew, eS[i]);

        if (rg == 0)
            o[((size_t)t * NH + h) * DV + col] = fmaf(d, vnew, c);
    };

    float eA[8], kA[8], qA[8], vA, bA;
    float eB[8], kB[8], qB[8], vB, bB;
    loadstep(0, eA, kA, qA, vA, bA);
    loadstep(1, eB, kB, qB, vB, bB);

#pragma unroll 1
    for (int t = 0; t < SQ; t += 2) {
        float eC[8], kC[8], qC[8], vC, bC;
        loadstep(t + 2, eC, kC, qC, vC, bC);
        step(t, eA, kA, qA, vA, bA);

        float eD[8], kD[8], qD[8], vD, bD;
        loadstep(t + 3, eD, kD, qD, vD, bD);
        step(t + 1, eB, kB, qB, vB, bB);

#pragma unroll
        for (int i = 0; i < 8; i++) {
            eA[i] = eC[i]; kA[i] = kC[i]; qA[i] = qC[i];
            eB[i] = eD[i]; kB[i] = kD[i]; qB[i] = qD[i];
        }
        vA = vC; bA = bC; vB = vD; bB = bD;
    }
}

// ================= post: gated rmsnorm + tf32 rounding =================
__global__ void post_kernel(float* __restrict__ o, const float* __restrict__ goutp,
                            const float* __restrict__ bg2, const float* __restrict__ wn)
{
    const int s = blockIdx.x;
    const int h = threadIdx.x >> 5;
    const int l = threadIdx.x & 31;
    const size_t base = ((size_t)s * NH + h) * DV + l * 4;

    float4 ov = *reinterpret_cast<float4*>(o + base);
    float ss = ov.x * ov.x + ov.y * ov.y + ov.z * ov.z + ov.w * ov.w;
#pragma unroll
    for (int off = 16; off; off >>= 1) ss += __shfl_xor_sync(0xffffffffu, ss, off);
    const float r = rsqrtf(ss * (1.f / DV) + 1e-5f);

    const int j = h * DV + l * 4;
    float4 gv = *reinterpret_cast<const float4*>(goutp + (size_t)s * DMODEL + j);
    float4 bb = *reinterpret_cast<const float4*>(bg2 + j);
    float4 wv = *reinterpret_cast<const float4*>(wn + l * 4);
    ov.x = ov.x * r * wv.x * (1.f / (1.f + expf(-(gv.x + bb.x))));
    ov.y = ov.y * r * wv.y * (1.f / (1.f + expf(-(gv.y + bb.y))));
    ov.z = ov.z * r * wv.z * (1.f / (1.f + expf(-(gv.z + bb.z))));
    ov.w = ov.w * r * wv.w * (1.f / (1.f + expf(-(gv.w + bb.w))));
    uint4 u;
    asm("cvt.rna.tf32.f32 %0, %1;" : "=r"(u.x) : "f"(ov.x));
    asm("cvt.rna.tf32.f32 %0, %1;" : "=r"(u.y) : "f"(ov.y));
    asm("cvt.rna.tf32.f32 %0, %1;" : "=r"(u.z) : "f"(ov.z));
    asm("cvt.rna.tf32.f32 %0, %1;" : "=r"(u.w) : "f"(ov.w));
    *reinterpret_cast<uint4*>(o + base) = u;
}

// ================= persistent streams/events =================
struct LaunchCtx {
    cudaStream_t s1, s2;
    cudaEvent_t evStart, evR, evJ1, evJ2;
    LaunchCtx() {
        cudaStreamCreateWithFlags(&s1, cudaStreamNonBlocking);
        cudaStreamCreateWithFlags(&s2, cudaStreamNonBlocking);
        cudaEventCreateWithFlags(&evStart, cudaEventDisableTiming);
        cudaEventCreateWithFlags(&evR,     cudaEventDisableTiming);
        cudaEventCreateWithFlags(&evJ1,    cudaEventDisableTiming);
        cudaEventCreateWithFlags(&evJ2,    cudaEventDisableTiming);
        cudaFuncSetAttribute(gemm_tf32,    cudaFuncAttributeMaxDynamicSharedMemorySize, GSMEM_V2);
        cudaFuncSetAttribute(gemm_tf32_b4, cudaFuncAttributeMaxDynamicSharedMemorySize, GSMEM_V2);
    }
};
static LaunchCtx& launch_ctx() { static LaunchCtx c; return c; }

// ================= launch =================
extern "C" void kernel_launch(void* const* d_in, const int* in_sizes, int n_in,
                              void* d_out, int out_size)
{
    const float* x       = (const float*)d_in[0];
    const float* ve      = (const float*)d_in[1];
    const float* lam     = (const float*)d_in[2];
    const float* Wq      = (const float*)d_in[3];
    const float* Wk      = (const float*)d_in[4];
    const float* Wv      = (const float*)d_in[5];
    const float* Wo      = (const float*)d_in[6];
    const float* wq_conv = (const float*)d_in[7];
    const float* wk_conv = (const float*)d_in[8];
    const float* wv_conv = (const float*)d_in[9];
    const float* Wf1     = (const float*)d_in[10];
    const float* Wf2     = (const float*)d_in[11];
    const float* Wb      = (const float*)d_in[12];
    const float* A_log   = (const float*)d_in[13];
    const float* dt_bias = (const float*)d_in[14];
    const float* Wg1     = (const float*)d_in[15];
    const float* Wg2     = (const float*)d_in[16];
    const float* bg2     = (const float*)d_in[17];
    const float* w_norm  = (const float*)d_in[18];
    float* out = (float*)d_out;

    float* sp = nullptr;
    cudaGetSymbolAddress((void**)&sp, g_scratch);

    float* xq   = sp + OFF_XQ;
    float* xk   = sp + OFF_XK;
    float* xv   = sp + OFF_XV;
    float* xve  = sp + OFF_XVE;
    float* cq   = sp + OFF_CQ;
    float* ck   = sp + OFF_CK;
    float* cv   = sp + OFF_CV;
    float* gpre = sp + OFF_GPRE;
    float* gout = sp + OFF_GOUT;
    float* obuf = sp + OFF_O;
    float* xr   = sp + OFF_XR;
    float* ver  = sp + OFF_VER;
    float* wqr  = sp + OFF_WQR;
    float* wkr  = sp + OFF_WKR;
    float* wvr  = sp + OFF_WVR;
    float* wor  = sp + OFF_WOR;
    float* wg1r = sp + OFF_WG1R;
    float* wg2r = sp + OFF_WG2R;
    float* f1   = sp + OFF_F1;
    float* g1   = sp + OFF_G1;
    float* bpre = sp + OFF_BPRE;

    LaunchCtx& cx = launch_ctx();

    const int nSD = SQ * DMODEL;
    const int EW = (nSD + 255) / 256;
    const dim3 gFat(DMODEL / 128, SQ / 128);   // (8,16)

    // ---- fork s1 at start: decay-gate path + beta need only raw inputs ----
    cudaEventRecord(cx.evStart, 0);
    cudaStreamWaitEvent(cx.s1, cx.evStart, 0);

    sgemm_nt_sk<<<dim3(1, SQ / 32), 256, 0, cx.s1>>>(x, Wf1, f1, SQ, DMODEL);
    sgemm_gate<<<gFat, 256, 0, cx.s1>>>(f1, Wf2, gpre, SQ, DMODEL, 128, A_log, dt_bias);
    beta_kernel<<<SQ, 256, 0, cx.s1>>>(x, Wb, bpre);

    // ---- s0: fused tf32 rounding of everything ----
    RoundPack rp;
    rp.src[0] = x;   rp.dst[0] = xr;   rp.n4[0] = nSD / 4;
    rp.src[1] = ve;  rp.dst[1] = ver;  rp.n4[1] = nSD / 4;
    rp.src[2] = Wq;  rp.dst[2] = wqr;  rp.n4[2] = 1048576 / 4;
    rp.src[3] = Wk;  rp.dst[3] = wkr;  rp.n4[3] = 1048576 / 4;
    rp.src[4] = Wv;  rp.dst[4] = wvr;  rp.n4[4] = 1048576 / 4;
    rp.src[5] = Wo;  rp.dst[5] = wor;  rp.n4[5] = 1048576 / 4;
    rp.src[6] = Wg1; rp.dst[6] = wg1r; rp.n4[6] = 131072 / 4;
    rp.src[7] = Wg2; rp.dst[7] = wg2r; rp.n4[7] = 131072 / 4;
    round_all_kernel<<<dim3((nSD / 4 + 255) / 256, 8), 256>>>(rp);
    cudaEventRecord(cx.evR, 0);

    // ---- s1 continues: output-gate path (g1 rounds its own output) ----
    cudaStreamWaitEvent(cx.s1, cx.evR, 0);
    gemm_tf32_64r<<<dim3(2, SQ / 64), 128, 0, cx.s1>>>(xr, wg1r, g1, SQ, 128, DMODEL);
    gemm_tf32<<<gFat, 256, GSMEM_V2, cx.s1>>>(g1, wg2r, gout, SQ, DMODEL, 128);
    cudaEventRecord(cx.evJ1, cx.s1);

    // ---- s0: all 4 fat projections in ONE batched launch ----
    Gemm4 g4;
    g4.A[0] = xr;  g4.B[0] = wqr; g4.C[0] = xq;
    g4.A[1] = xr;  g4.B[1] = wkr; g4.C[1] = xk;
    g4.A[2] = xr;  g4.B[2] = wvr; g4.C[2] = xv;
    g4.A[3] = ver; g4.B[3] = wvr; g4.C[3] = xve;
    gemm_tf32_b4<<<dim3(DMODEL / 128, SQ / 128, 4), 256, GSMEM_V2>>>(g4, DMODEL, DMODEL);

    // ---- s2: conv-mix for v (needs xv, xve from batch) ----
    cudaEventRecord(cx.evJ2, 0);
    cudaStreamWaitEvent(cx.s2, cx.evJ2, 0);
    convmix_silu_kernel<<<EW, 256, 0, cx.s2>>>(xv, xve, wv_conv, lam, cv, nSD);
    cudaEventRecord(cx.evJ2, cx.s2);

    // ---- s0: fused conv+silu+l2norm for q/k ----
    conv_l2_qk_kernel<<<SQ, 256>>>(xq, xk, wq_conv, wk_conv, cq, ck);

    // ---- join, then sequential tail ----
    cudaStreamWaitEvent(0, cx.evJ1, 0);
    cudaStreamWaitEvent(0, cx.evJ2, 0);

    kda_scan_kernel<<<NH * 16, 128>>>(cq, ck, cv, gpre, bpre, obuf);
    post_kernel<<<SQ, 256>>>(obuf, gout, bg2, w_norm);
    gemm_tf32<<<gFat, 256, GSMEM_V2>>>(obuf, wor, out, SQ, DMODEL, DMODEL);
}

// round 16
// speedup vs baseline: 1.0817x; 1.0817x over previous
#include <cuda_runtime.h>
#include <mma.h>
#include <cstdint>
#include <cstddef>

using namespace nvcuda;

#define SQ     2048
#define DMODEL 1024
#define NH     8
#define DK     128
#define DV     128
#define KCONV  4

// ---------------- scratch ----------------
#define NBIGF   (2097152)              // SQ*DMODEL
#define OFF_XQ   ((size_t)0  * NBIGF)
#define OFF_XK   ((size_t)1  * NBIGF)
#define OFF_XV   ((size_t)2  * NBIGF)
#define OFF_XVE  ((size_t)3  * NBIGF)
#define OFF_CQ   ((size_t)4  * NBIGF)
#define OFF_CK   ((size_t)5  * NBIGF)
#define OFF_CV   ((size_t)6  * NBIGF)
#define OFF_GPRE ((size_t)7  * NBIGF)
#define OFF_GOUT ((size_t)8  * NBIGF)
#define OFF_O    ((size_t)9  * NBIGF)
#define OFF_XR   ((size_t)10 * NBIGF)
#define OFF_VER  ((size_t)11 * NBIGF)
#define OFF_WQR  ((size_t)12 * NBIGF)
#define OFF_WKR  (OFF_WQR + (size_t)1048576)
#define OFF_WVR  (OFF_WKR + (size_t)1048576)
#define OFF_WOR  (OFF_WVR + (size_t)1048576)
#define OFF_WG1R (OFF_WOR + (size_t)1048576)
#define OFF_WG2R (OFF_WG1R + (size_t)131072)
#define OFF_F1   (OFF_WG2R + (size_t)131072)
#define OFF_G1   (OFF_F1 + (size_t)SQ*128)
#define OFF_BPRE (OFF_G1 + (size_t)SQ*128)
#define OFF_QK   (OFF_BPRE + (size_t)SQ*NH)
#define SCRATCH_FLOATS (OFF_QK + (size_t)SQ*NH)

__device__ float g_scratch[SCRATCH_FLOATS];

// ================= helpers =================
__device__ __forceinline__ uint32_t smem_u32(const void* p) {
    uint32_t a;
    asm("{ .reg .u64 t; cvta.to.shared.u64 t, %1; cvt.u32.u64 %0, t; }" : "=r"(a) : "l"(p));
    return a;
}
__device__ __forceinline__ void cp16(uint32_t saddr, const void* g) {
    asm volatile("cp.async.cg.shared.global [%0], [%1], 16;" :: "r"(saddr), "l"(g));
}
#define CP_COMMIT() asm volatile("cp.async.commit_group;" ::: "memory")

// ================= WMMA tf32 NT GEMM (128x128 tile, BK=16, double-buffered) =================
#define BK 16
#define LDS_PAD 4
#define LDS_STRIDE (BK + LDS_PAD)   // 20

__device__ __forceinline__ void gemm128_body(
    const float* __restrict__ A, const float* __restrict__ B,
    float* __restrict__ C, int N, int K, int rowBlk, int colBlk)
{
    __shared__ __align__(16) float As[2][128][LDS_STRIDE];
    __shared__ __align__(16) float Bs[2][128][LDS_STRIDE];

    const int tid = threadIdx.x;
    const int wid = tid >> 5;
    const int wr = wid >> 1;
    const int wc = wid & 1;

    const int lr = tid >> 1;
    const int lc = (tid & 1) * 8;
    const float* gA = A + (size_t)(rowBlk + lr) * K + lc;
    const float* gB = B + (size_t)(colBlk + lr) * K + lc;

    wmma::fragment<wmma::accumulator, 16, 16, 8, float> acc[2][4];
#pragma unroll
    for (int i = 0; i < 2; i++)
#pragma unroll
        for (int j = 0; j < 4; j++) wmma::fill_fragment(acc[i][j], 0.f);

    auto load_tile = [&](int k0, int st) {
        cp16(smem_u32(&As[st][lr][lc]),     gA + k0);
        cp16(smem_u32(&As[st][lr][lc + 4]), gA + k0 + 4);
        cp16(smem_u32(&Bs[st][lr][lc]),     gB + k0);
        cp16(smem_u32(&Bs[st][lr][lc + 4]), gB + k0 + 4);
    };

    const int nk = K / BK;
    load_tile(0, 0);
    CP_COMMIT();

    for (int i = 0; i < nk; i++) {
        const int st = i & 1;
        if (i + 1 < nk) {
            load_tile((i + 1) * BK, st ^ 1);
            CP_COMMIT();
            asm volatile("cp.async.wait_group 1;" ::: "memory");
        } else {
            asm volatile("cp.async.wait_group 0;" ::: "memory");
        }
        __syncthreads();

#pragma unroll
        for (int kk = 0; kk < BK; kk += 8) {
            wmma::fragment<wmma::matrix_a, 16, 16, 8, wmma::precision::tf32, wmma::row_major> af[2];
            wmma::fragment<wmma::matrix_b, 16, 16, 8, wmma::precision::tf32, wmma::col_major> bf[4];
#pragma unroll
            for (int i2 = 0; i2 < 2; i2++)
                wmma::load_matrix_sync(af[i2], &As[st][wr * 32 + i2 * 16][kk], LDS_STRIDE);
#pragma unroll
            for (int j = 0; j < 4; j++)
                wmma::load_matrix_sync(bf[j], &Bs[st][wc * 64 + j * 16][kk], LDS_STRIDE);
#pragma unroll
            for (int i2 = 0; i2 < 2; i2++)
#pragma unroll
                for (int j = 0; j < 4; j++)
                    wmma::mma_sync(acc[i2][j], af[i2], bf[j], acc[i2][j]);
        }
        __syncthreads();
    }

#pragma unroll
    for (int i = 0; i < 2; i++)
#pragma unroll
        for (int j = 0; j < 4; j++)
            wmma::store_matrix_sync(
                C + (size_t)(rowBlk + wr * 32 + i * 16) * N + colBlk + wc * 64 + j * 16,
                acc[i][j], N, wmma::mem_row_major);
}

__global__ void __launch_bounds__(256) gemm_tf32(
    const float* __restrict__ A, const float* __restrict__ B,
    float* __restrict__ C, int M, int N, int K)
{
    gemm128_body(A, B, C, N, K, blockIdx.y * 128, blockIdx.x * 128);
}

struct Gemm4 { const float* A[4]; const float* B[4]; float* C[4]; };

__global__ void __launch_bounds__(256) gemm_tf32_b4(Gemm4 p, int N, int K)
{
    const int z = blockIdx.z;
    gemm128_body(p.A[z], p.B[z], p.C[z], N, K, blockIdx.y * 128, blockIdx.x * 128);
}

// ================= WMMA tf32 64x64-tile GEMM with tf32-rounded output =================
__global__ void __launch_bounds__(128) gemm_tf32_64r(
    const float* __restrict__ A, const float* __restrict__ B,
    float* __restrict__ C, int M, int N, int K)
{
    __shared__ __align__(16) float As[2][64][LDS_STRIDE];
    __shared__ __align__(16) float Bs[2][64][LDS_STRIDE];

    const int tid = threadIdx.x;
    const int wid = tid >> 5;
    const int wr = wid >> 1;
    const int wc = wid & 1;
    const int rowBlk = blockIdx.y * 64;
    const int colBlk = blockIdx.x * 64;

    const int lr = tid >> 1;
    const int lc = (tid & 1) * 8;
    const float* gA = A + (size_t)(rowBlk + lr) * K + lc;
    const float* gB = B + (size_t)(colBlk + lr) * K + lc;

    wmma::fragment<wmma::accumulator, 16, 16, 8, float> acc[2][2];
#pragma unroll
    for (int i = 0; i < 2; i++)
#pragma unroll
        for (int j = 0; j < 2; j++) wmma::fill_fragment(acc[i][j], 0.f);

    auto load_tile = [&](int k0, int st) {
        cp16(smem_u32(&As[st][lr][lc]),     gA + k0);
        cp16(smem_u32(&As[st][lr][lc + 4]), gA + k0 + 4);
        cp16(smem_u32(&Bs[st][lr][lc]),     gB + k0);
        cp16(smem_u32(&Bs[st][lr][lc + 4]), gB + k0 + 4);
    };

    const int nk = K / BK;
    load_tile(0, 0);
    CP_COMMIT();

    for (int i = 0; i < nk; i++) {
        const int st = i & 1;
        if (i + 1 < nk) {
            load_tile((i + 1) * BK, st ^ 1);
            CP_COMMIT();
            asm volatile("cp.async.wait_group 1;" ::: "memory");
        } else {
            asm volatile("cp.async.wait_group 0;" ::: "memory");
        }
        __syncthreads();

#pragma unroll
        for (int kk = 0; kk < BK; kk += 8) {
            wmma::fragment<wmma::matrix_a, 16, 16, 8, wmma::precision::tf32, wmma::row_major> af[2];
            wmma::fragment<wmma::matrix_b, 16, 16, 8, wmma::precision::tf32, wmma::col_major> bf[2];
#pragma unroll
            for (int i2 = 0; i2 < 2; i2++)
                wmma::load_matrix_sync(af[i2], &As[st][wr * 32 + i2 * 16][kk], LDS_STRIDE);
#pragma unroll
            for (int j = 0; j < 2; j++)
                wmma::load_matrix_sync(bf[j], &Bs[st][wc * 32 + j * 16][kk], LDS_STRIDE);
#pragma unroll
            for (int i2 = 0; i2 < 2; i2++)
#pragma unroll
                for (int j = 0; j < 2; j++)
                    wmma::mma_sync(acc[i2][j], af[i2], bf[j], acc[i2][j]);
        }
        __syncthreads();
    }

#pragma unroll
    for (int i = 0; i < 2; i++)
#pragma unroll
        for (int j = 0; j < 2; j++) {
#pragma unroll
            for (int e = 0; e < acc[i][j].num_elements; e++) {
                uint32_t u;
                asm("cvt.rna.tf32.f32 %0, %1;" : "=r"(u) : "f"(acc[i][j].x[e]));
                acc[i][j].x[e] = __uint_as_float(u);
            }
            wmma::store_matrix_sync(
                C + (size_t)(rowBlk + wr * 32 + i * 16) * N + colBlk + wc * 32 + j * 16,
                acc[i][j], N, wmma::mem_row_major);
        }
}

// ================= fp32 SIMT GEMMs (accuracy-critical decay path) =================
__global__ void __launch_bounds__(256) sgemm_gate(
    const float* __restrict__ A, const float* __restrict__ B,
    float* __restrict__ C, int M, int N, int Ksz,
    const float* __restrict__ A_log, const float* __restrict__ dt_bias)
{
    __shared__ __align__(16) float As2[16][128];
    __shared__ __align__(16) float Bs2[16][128];

    const int tid = threadIdx.x;
    const int tx = tid & 15;
    const int ty = tid >> 4;
    const int rowC = blockIdx.y * 128 + ty * 8;
    const int colC = blockIdx.x * 128 + tx * 8;
    const int lrow = tid >> 2;
    const int lk   = (tid & 3) * 4;

    float acc[8][8];
#pragma unroll
    for (int i = 0; i < 8; i++)
#pragma unroll
        for (int j = 0; j < 8; j++) acc[i][j] = 0.f;

    for (int k0 = 0; k0 < Ksz; k0 += 16) {
#pragma unroll
        for (int rr = 0; rr < 2; rr++) {
            const int r = lrow + rr * 64;
            {
                const int grow = blockIdx.y * 128 + r;
                float4 av = make_float4(0.f, 0.f, 0.f, 0.f);
                if (grow < M)
                    av = *reinterpret_cast<const float4*>(A + (size_t)grow * Ksz + k0 + lk);
                As2[lk + 0][r] = av.x; As2[lk + 1][r] = av.y;
                As2[lk + 2][r] = av.z; As2[lk + 3][r] = av.w;
            }
            {
                const int gcol = blockIdx.x * 128 + r;
                float4 bv = make_float4(0.f, 0.f, 0.f, 0.f);
                if (gcol < N)
                    bv = *reinterpret_cast<const float4*>(B + (size_t)gcol * Ksz + k0 + lk);
                Bs2[lk + 0][r] = bv.x; Bs2[lk + 1][r] = bv.y;
                Bs2[lk + 2][r] = bv.z; Bs2[lk + 3][r] = bv.w;
            }
        }
        __syncthreads();
#pragma unroll
        for (int kk = 0; kk < 16; kk++) {
            float a[8], b[8];
            *reinterpret_cast<float4*>(a)     = *reinterpret_cast<const float4*>(&As2[kk][ty * 8]);
            *reinterpret_cast<float4*>(a + 4) = *reinterpret_cast<const float4*>(&As2[kk][ty * 8 + 4]);
            *reinterpret_cast<float4*>(b)     = *reinterpret_cast<const float4*>(&Bs2[kk][tx * 8]);
            *reinterpret_cast<float4*>(b + 4) = *reinterpret_cast<const float4*>(&Bs2[kk][tx * 8 + 4]);
#pragma unroll
            for (int i = 0; i < 8; i++)
#pragma unroll
                for (int j = 0; j < 8; j++)
                    acc[i][j] = fmaf(a[i], b[j], acc[i][j]);
        }
        __syncthreads();
    }
#pragma unroll
    for (int i = 0; i < 8; i++) {
        const int r = rowC + i;
        if (r >= M) continue;
#pragma unroll
        for (int j = 0; j < 8; j++) {
            const int c = colC + j;
            if (c < N) {
                float xv = acc[i][j] + dt_bias[c];
                float spv = fmaxf(xv, 0.f) + log1pf(expf(-fabsf(xv)));
                C[(size_t)r * N + c] = expf(-expf(A_log[c >> 7]) * spv);
            }
        }
    }
}

__global__ void __launch_bounds__(256) sgemm_nt_sk(
    const float* __restrict__ A, const float* __restrict__ B,
    float* __restrict__ C, int M, int Ksz)
{
    __shared__ __align__(16) float As3[16][32];
    __shared__ __align__(16) float Bs3[16][128];

    const int tid = threadIdx.x;
    const int tx = tid & 15;
    const int ty = tid >> 4;
    const int rowBlk = blockIdx.y * 32;

    const int arow = tid >> 3;
    const int ak   = (tid & 7) * 2;
    const int brow = tid >> 1;
    const int bk   = (tid & 1) * 8;

    float acc[2][8];
#pragma unroll
    for (int i = 0; i < 2; i++)
#pragma unroll
        for (int j = 0; j < 8; j++) acc[i][j] = 0.f;

    for (int k0 = 0; k0 < Ksz; k0 += 16) {
        {
            float2 av = *reinterpret_cast<const float2*>(A + (size_t)(rowBlk + arow) * Ksz + k0 + ak);
            As3[ak + 0][arow] = av.x; As3[ak + 1][arow] = av.y;
        }
        {
            float4 b0 = *reinterpret_cast<const float4*>(B + (size_t)brow * Ksz + k0 + bk);
            float4 b1 = *reinterpret_cast<const float4*>(B + (size_t)brow * Ksz + k0 + bk + 4);
            Bs3[bk + 0][brow] = b0.x; Bs3[bk + 1][brow] = b0.y;
            Bs3[bk + 2][brow] = b0.z; Bs3[bk + 3][brow] = b0.w;
            Bs3[bk + 4][brow] = b1.x; Bs3[bk + 5][brow] = b1.y;
            Bs3[bk + 6][brow] = b1.z; Bs3[bk + 7][brow] = b1.w;
        }
        __syncthreads();
#pragma unroll
        for (int kk = 0; kk < 16; kk++) {
            float a0 = As3[kk][ty * 2], a1 = As3[kk][ty * 2 + 1];
            float b[8];
            *reinterpret_cast<float4*>(b)     = *reinterpret_cast<const float4*>(&Bs3[kk][tx * 8]);
            *reinterpret_cast<float4*>(b + 4) = *reinterpret_cast<const float4*>(&Bs3[kk][tx * 8 + 4]);
#pragma unroll
            for (int j = 0; j < 8; j++) {
                acc[0][j] = fmaf(a0, b[j], acc[0][j]);
                acc[1][j] = fmaf(a1, b[j], acc[1][j]);
            }
        }
        __syncthreads();
    }
#pragma unroll
    for (int i = 0; i < 2; i++) {
        float* cp = C + (size_t)(rowBlk + ty * 2 + i) * 128 + tx * 8;
#pragma unroll
        for (int j = 0; j < 8; j++) cp[j] = acc[i][j];
    }
}

// ================= fused tf32 rounding =================
struct RoundPack {
    const float* src[8];
    float* dst[8];
    int n4[8];
};

__global__ void round_all_kernel(RoundPack p)
{
    const int r = blockIdx.y;
    const int i = blockIdx.x * blockDim.x + threadIdx.x;
    if (i >= p.n4[r]) return;
    float4 v = reinterpret_cast<const float4*>(p.src[r])[i];
    uint4 u;
    asm("cvt.rna.tf32.f32 %0, %1;" : "=r"(u.x) : "f"(v.x));
    asm("cvt.rna.tf32.f32 %0, %1;" : "=r"(u.y) : "f"(v.y));
    asm("cvt.rna.tf32.f32 %0, %1;" : "=r"(u.z) : "f"(v.z));
    asm("cvt.rna.tf32.f32 %0, %1;" : "=r"(u.w) : "f"(v.w));
    reinterpret_cast<uint4*>(p.dst[r])[i] = u;
}

// ================= fused conv+silu+l2norm for q/k + q·k dot precompute =================
__global__ void __launch_bounds__(256) conv_l2_qk_kernel(
    const float* __restrict__ xq, const float* __restrict__ xk,
    const float* __restrict__ wqc, const float* __restrict__ wkc,
    float* __restrict__ cq, float* __restrict__ ck,
    float* __restrict__ qk)
{
    const int s = blockIdx.x;
    const int tid = threadIdx.x;
    const int d = tid * 4;
    const int h = tid >> 5;
    const int l = tid & 31;

    float wq[4][4], wk[4][4];
#pragma unroll
    for (int c = 0; c < 4; c++) {
        float4 a = *reinterpret_cast<const float4*>(wqc + (d + c) * 4);
        wq[c][0] = a.x; wq[c][1] = a.y; wq[c][2] = a.z; wq[c][3] = a.w;
        float4 b = *reinterpret_cast<const float4*>(wkc + (d + c) * 4);
        wk[c][0] = b.x; wk[c][1] = b.y; wk[c][2] = b.z; wk[c][3] = b.w;
    }

    float aq[4] = {0.f, 0.f, 0.f, 0.f};
    float ak[4] = {0.f, 0.f, 0.f, 0.f};
#pragma unroll
    for (int i = 0; i < KCONV; i++) {
        const int sp = s - (KCONV - 1) + i;
        if (sp >= 0) {
            float4 xv = *reinterpret_cast<const float4*>(xq + (size_t)sp * DMODEL + d);
            aq[0] = fmaf(xv.x, wq[0][i], aq[0]);
            aq[1] = fmaf(xv.y, wq[1][i], aq[1]);
            aq[2] = fmaf(xv.z, wq[2][i], aq[2]);
            aq[3] = fmaf(xv.w, wq[3][i], aq[3]);
            float4 kv = *reinterpret_cast<const float4*>(xk + (size_t)sp * DMODEL + d);
            ak[0] = fmaf(kv.x, wk[0][i], ak[0]);
            ak[1] = fmaf(kv.y, wk[1][i], ak[1]);
            ak[2] = fmaf(kv.z, wk[2][i], ak[2]);
            ak[3] = fmaf(kv.w, wk[3][i], ak[3]);
        }
    }

    float ssq = 0.f, ssk = 0.f;
#pragma unroll
    for (int c = 0; c < 4; c++) {
        aq[c] = aq[c] / (1.f + expf(-aq[c]));
        ak[c] = ak[c] / (1.f + expf(-ak[c]));
        ssq = fmaf(aq[c], aq[c], ssq);
        ssk = fmaf(ak[c], ak[c], ssk);
    }
#pragma unroll
    for (int o = 16; o; o >>= 1) {
        ssq += __shfl_xor_sync(0xffffffffu, ssq, o);
        ssk += __shfl_xor_sync(0xffffffffu, ssk, o);
    }
    const float rq = rsqrtf(ssq + 1e-6f) * 0.08838834764831845f;
    const float rk = rsqrtf(ssk + 1e-6f);

    float4 oq = make_float4(aq[0] * rq, aq[1] * rq, aq[2] * rq, aq[3] * rq);
    float4 ok = make_float4(ak[0] * rk, ak[1] * rk, ak[2] * rk, ak[3] * rk);
    *reinterpret_cast<float4*>(cq + (size_t)s * DMODEL + d) = oq;
    *reinterpret_cast<float4*>(ck + (size_t)s * DMODEL + d) = ok;

    // q·k dot per (s, head) — removes the state-independent tree from the scan
    float dt = oq.x * ok.x + oq.y * ok.y + oq.z * ok.z + oq.w * ok.w;
#pragma unroll
    for (int o = 16; o; o >>= 1) dt += __shfl_xor_sync(0xffffffffu, dt, o);
    if (l == 0) qk[(size_t)s * NH + h] = dt;
}

__global__ void convmix_silu_kernel(const float* __restrict__ xv,
                                    const float* __restrict__ xve,
                                    const float* __restrict__ w,
                                    const float* __restrict__ lam,
                                    float* __restrict__ out, int n)
{
    int idx = blockIdx.x * blockDim.x + threadIdx.x;
    if (idx >= n) return;
    int s = idx >> 10;
    int d = idx & 1023;
    float a = 0.f, b = 0.f;
#pragma unroll
    for (int i = 0; i < KCONV; i++) {
        int sp = s - (KCONV - 1) + i;
        if (sp >= 0) {
            const float wt = w[d * KCONV + i];
            a = fmaf(xv[(size_t)sp * DMODEL + d], wt, a);
            b = fmaf(xve[(size_t)sp * DMODEL + d], wt, b);
        }
    }
    const float sa = a / (1.f + expf(-a));
    const float sb = b / (1.f + expf(-b));
    out[idx] = lam[0] * sa + lam[1] * sb;
}

__global__ void __launch_bounds__(256) beta_kernel(const float* __restrict__ x,
                                                   const float* __restrict__ Wb,
                                                   float* __restrict__ out)
{
    const int s = blockIdx.x;
    const int h = threadIdx.x >> 5;
    const int l = threadIdx.x & 31;
    float acc = 0.f;
#pragma unroll
    for (int j = 0; j < 8; j++) {
        float4 xv = *reinterpret_cast<const float4*>(x + (size_t)s * DMODEL + j * 128 + l * 4);
        float4 wv = *reinterpret_cast<const float4*>(Wb + (size_t)h * DMODEL + j * 128 + l * 4);
        acc = fmaf(xv.x, wv.x, acc); acc = fmaf(xv.y, wv.y, acc);
        acc = fmaf(xv.z, wv.z, acc); acc = fmaf(xv.w, wv.w, acc);
    }
#pragma unroll
    for (int o = 16; o; o >>= 1) acc += __shfl_xor_sync(0xffffffffu, acc, o);
    if (l == 0) out[(size_t)s * NH + h] = 1.f / (1.f + expf(-acc));
}

// ================= KDA scan: a-tree only on critical path =================
// step: eS = e*S ; a = Σ k·eS (4-shfl tree) ; vnew = (v-a)β ; S = eS + k·vnew ;
// then (off-path) c = Σ q·eS tree ; o = c + qk·vnew.
__global__ void __launch_bounds__(128) kda_scan_kernel(
    const float* __restrict__ qn, const float* __restrict__ kn,
    const float* __restrict__ v,  const float* __restrict__ ed,
    const float* __restrict__ beta, const float* __restrict__ qk,
    float* __restrict__ o)
{
    const int h  = blockIdx.x >> 4;
    const int cg = blockIdx.x & 15;
    const int w  = threadIdx.x >> 5;
    const int l  = threadIdx.x & 31;
    const int cw = l >> 4;
    const int rg = l & 15;
    const int col = cg * 8 + w * 2 + cw;
    const int r0  = rg * 8;

    float S[8];
#pragma unroll
    for (int i = 0; i < 8; i++) S[i] = 0.f;

    auto loadstep = [&](int t, float* e, float* k, float* q,
                        float& vv, float& bb, float& dd) {
        const int tt = t < SQ ? t : SQ - 1;
        const size_t base = ((size_t)tt * NH + h) * DK;
        float4 x0 = __ldg(reinterpret_cast<const float4*>(ed + base + r0));
        float4 x1 = __ldg(reinterpret_cast<const float4*>(ed + base + r0 + 4));
        e[0] = x0.x; e[1] = x0.y; e[2] = x0.z; e[3] = x0.w;
        e[4] = x1.x; e[5] = x1.y; e[6] = x1.z; e[7] = x1.w;
        x0 = __ldg(reinterpret_cast<const float4*>(kn + base + r0));
        x1 = __ldg(reinterpret_cast<const float4*>(kn + base + r0 + 4));
        k[0] = x0.x; k[1] = x0.y; k[2] = x0.z; k[3] = x0.w;
        k[4] = x1.x; k[5] = x1.y; k[6] = x1.z; k[7] = x1.w;
        x0 = __ldg(reinterpret_cast<const float4*>(qn + base + r0));
        x1 = __ldg(reinterpret_cast<const float4*>(qn + base + r0 + 4));
        q[0] = x0.x; q[1] = x0.y; q[2] = x0.z; q[3] = x0.w;
        q[4] = x1.x; q[5] = x1.y; q[6] = x1.z; q[7] = x1.w;
        vv = __ldg(v + ((size_t)tt * NH + h) * DV + col);
        bb = __ldg(beta + (size_t)tt * NH + h);
        dd = __ldg(qk + (size_t)tt * NH + h);
    };

    auto step = [&](int t, const float* e, const float* k, const float* q,
                    float vc, float bt, float dd) {
        float eS[8];
#pragma unroll
        for (int i = 0; i < 8; i++) eS[i] = e[i] * S[i];

        float a0 = 0.f, a1 = 0.f, a2 = 0.f, a3 = 0.f;
        float c0 = 0.f, c1 = 0.f, c2 = 0.f, c3 = 0.f;
#pragma unroll
        for (int i = 0; i < 8; i += 4) {
            a0 = fmaf(k[i + 0], eS[i + 0], a0);
            a1 = fmaf(k[i + 1], eS[i + 1], a1);
            a2 = fmaf(k[i + 2], eS[i + 2], a2);
            a3 = fmaf(k[i + 3], eS[i + 3], a3);
            c0 = fmaf(q[i + 0], eS[i + 0], c0);
            c1 = fmaf(q[i + 1], eS[i + 1], c1);
            c2 = fmaf(q[i + 2], eS[i + 2], c2);
            c3 = fmaf(q[i + 3], eS[i + 3], c3);
        }
        float a = (a0 + a1) + (a2 + a3);

        // critical path: a-tree only
#pragma unroll
        for (int off = 1; off < 16; off <<= 1)
            a += __shfl_xor_sync(0xffffffffu, a, off);

        const float vnew = (vc - a) * bt;
#pragma unroll
        for (int i = 0; i < 8; i++) S[i] = fmaf(k[i], vnew, eS[i]);

        // off-path: c-tree + output
        float c = (c0 + c1) + (c2 + c3);
#pragma unroll
        for (int off = 1; off < 16; off <<= 1)
            c += __shfl_xor_sync(0xffffffffu, c, off);
        if (rg == 0)
            o[((size_t)t * NH + h) * DV + col] = fmaf(dd, vnew, c);
    };

    float eA[8], kA[8], qA[8], vA, bA, dA;
    float eB[8], kB[8], qB[8], vB, bB, dB;
    loadstep(0, eA, kA, qA, vA, bA, dA);
    loadstep(1, eB, kB, qB, vB, bB, dB);

#pragma unroll 1
    for (int t = 0; t < SQ; t += 2) {
        float eC[8], kC[8], qC[8], vC, bC, dC;
        loadstep(t + 2, eC, kC, qC, vC, bC, dC);
        step(t, eA, kA, qA, vA, bA, dA);

        float eD[8], kD[8], qD[8], vD, bD, dD;
        loadstep(t + 3, eD, kD, qD, vD, bD, dD);
        step(t + 1, eB, kB, qB, vB, bB, dB);

#pragma unroll
        for (int i = 0; i < 8; i++) {
            eA[i] = eC[i]; kA[i] = kC[i]; qA[i] = qC[i];
            eB[i] = eD[i]; kB[i] = kD[i]; qB[i] = qD[i];
        }
        vA = vC; bA = bC; dA = dC; vB = vD; bB = bD; dB = dD;
    }
}

// ================= post: gated rmsnorm + tf32 rounding =================
__global__ void post_kernel(float* __restrict__ o, const float* __restrict__ goutp,
                            const float* __restrict__ bg2, const float* __restrict__ wn)
{
    const int s = blockIdx.x;
    const int h = threadIdx.x >> 5;
    const int l = threadIdx.x & 31;
    const size_t base = ((size_t)s * NH + h) * DV + l * 4;

    float4 ov = *reinterpret_cast<float4*>(o + base);
    float ss = ov.x * ov.x + ov.y * ov.y + ov.z * ov.z + ov.w * ov.w;
#pragma unroll
    for (int off = 16; off; off >>= 1) ss += __shfl_xor_sync(0xffffffffu, ss, off);
    const float r = rsqrtf(ss * (1.f / DV) + 1e-5f);

    const int j = h * DV + l * 4;
    float4 gv = *reinterpret_cast<const float4*>(goutp + (size_t)s * DMODEL + j);
    float4 bb = *reinterpret_cast<const float4*>(bg2 + j);
    float4 wv = *reinterpret_cast<const float4*>(wn + l * 4);
    ov.x = ov.x * r * wv.x * (1.f / (1.f + expf(-(gv.x + bb.x))));
    ov.y = ov.y * r * wv.y * (1.f / (1.f + expf(-(gv.y + bb.y))));
    ov.z = ov.z * r * wv.z * (1.f / (1.f + expf(-(gv.z + bb.z))));
    ov.w = ov.w * r * wv.w * (1.f / (1.f + expf(-(gv.w + bb.w))));
    uint4 u;
    asm("cvt.rna.tf32.f32 %0, %1;" : "=r"(u.x) : "f"(ov.x));
    asm("cvt.rna.tf32.f32 %0, %1;" : "=r"(u.y) : "f"(ov.y));
    asm("cvt.rna.tf32.f32 %0, %1;" : "=r"(u.z) : "f"(ov.z));
    asm("cvt.rna.tf32.f32 %0, %1;" : "=r"(u.w) : "f"(ov.w));
    *reinterpret_cast<uint4*>(o + base) = u;
}

// ================= persistent streams/events =================
struct LaunchCtx {
    cudaStream_t s1, s2;
    cudaEvent_t evStart, evR, evJ1, evJ2;
    LaunchCtx() {
        cudaStreamCreateWithFlags(&s1, cudaStreamNonBlocking);
        cudaStreamCreateWithFlags(&s2, cudaStreamNonBlocking);
        cudaEventCreateWithFlags(&evStart, cudaEventDisableTiming);
        cudaEventCreateWithFlags(&evR,     cudaEventDisableTiming);
        cudaEventCreateWithFlags(&evJ1,    cudaEventDisableTiming);
        cudaEventCreateWithFlags(&evJ2,    cudaEventDisableTiming);
    }
};
static LaunchCtx& launch_ctx() { static LaunchCtx c; return c; }

// ================= launch =================
extern "C" void kernel_launch(void* const* d_in, const int* in_sizes, int n_in,
                              void* d_out, int out_size)
{
    const float* x       = (const float*)d_in[0];
    const float* ve      = (const float*)d_in[1];
    const float* lam     = (const float*)d_in[2];
    const float* Wq      = (const float*)d_in[3];
    const float* Wk      = (const float*)d_in[4];
    const float* Wv      = (const float*)d_in[5];
    const float* Wo      = (const float*)d_in[6];
    const float* wq_conv = (const float*)d_in[7];
    const float* wk_conv = (const float*)d_in[8];
    const float* wv_conv = (const float*)d_in[9];
    const float* Wf1     = (const float*)d_in[10];
    const float* Wf2     = (const float*)d_in[11];
    const float* Wb      = (const float*)d_in[12];
    const float* A_log   = (const float*)d_in[13];
    const float* dt_bias = (const float*)d_in[14];
    const float* Wg1     = (const float*)d_in[15];
    const float* Wg2     = (const float*)d_in[16];
    const float* bg2     = (const float*)d_in[17];
    const float* w_norm  = (const float*)d_in[18];
    float* out = (float*)d_out;

    float* sp = nullptr;
    cudaGetSymbolAddress((void**)&sp, g_scratch);

    float* xq   = sp + OFF_XQ;
    float* xk   = sp + OFF_XK;
    float* xv   = sp + OFF_XV;
    float* xve  = sp + OFF_XVE;
    float* cq   = sp + OFF_CQ;
    float* ck   = sp + OFF_CK;
    float* cv   = sp + OFF_CV;
    float* gpre = sp + OFF_GPRE;
    float* gout = sp + OFF_GOUT;
    float* obuf = sp + OFF_O;
    float* xr   = sp + OFF_XR;
    float* ver  = sp + OFF_VER;
    float* wqr  = sp + OFF_WQR;
    float* wkr  = sp + OFF_WKR;
    float* wvr  = sp + OFF_WVR;
    float* wor  = sp + OFF_WOR;
    float* wg1r = sp + OFF_WG1R;
    float* wg2r = sp + OFF_WG2R;
    float* f1   = sp + OFF_F1;
    float* g1   = sp + OFF_G1;
    float* bpre = sp + OFF_BPRE;
    float* qkd  = sp + OFF_QK;

    LaunchCtx& cx = launch_ctx();

    const int nSD = SQ * DMODEL;
    const int EW = (nSD + 255) / 256;
    const dim3 gFat(DMODEL / 128, SQ / 128);   // (8,16)

    // ---- fork s1 at start: decay-gate path + beta need only raw inputs ----
    cudaEventRecord(cx.evStart, 0);
    cudaStreamWaitEvent(cx.s1, cx.evStart, 0);

    sgemm_nt_sk<<<dim3(1, SQ / 32), 256, 0, cx.s1>>>(x, Wf1, f1, SQ, DMODEL);
    sgemm_gate<<<gFat, 256, 0, cx.s1>>>(f1, Wf2, gpre, SQ, DMODEL, 128, A_log, dt_bias);
    beta_kernel<<<SQ, 256, 0, cx.s1>>>(x, Wb, bpre);

    // ---- s0: fused tf32 rounding of everything ----
    RoundPack rp;
    rp.src[0] = x;   rp.dst[0] = xr;   rp.n4[0] = nSD / 4;
    rp.src[1] = ve;  rp.dst[1] = ver;  rp.n4[1] = nSD / 4;
    rp.src[2] = Wq;  rp.dst[2] = wqr;  rp.n4[2] = 1048576 / 4;
    rp.src[3] = Wk;  rp.dst[3] = wkr;  rp.n4[3] = 1048576 / 4;
    rp.src[4] = Wv;  rp.dst[4] = wvr;  rp.n4[4] = 1048576 / 4;
    rp.src[5] = Wo;  rp.dst[5] = wor;  rp.n4[5] = 1048576 / 4;
    rp.src[6] = Wg1; rp.dst[6] = wg1r; rp.n4[6] = 131072 / 4;
    rp.src[7] = Wg2; rp.dst[7] = wg2r; rp.n4[7] = 131072 / 4;
    round_all_kernel<<<dim3((nSD / 4 + 255) / 256, 8), 256>>>(rp);
    cudaEventRecord(cx.evR, 0);

    // ---- s1 continues: output-gate path (g1 rounds its own output) ----
    cudaStreamWaitEvent(cx.s1, cx.evR, 0);
    gemm_tf32_64r<<<dim3(2, SQ / 64), 128, 0, cx.s1>>>(xr, wg1r, g1, SQ, 128, DMODEL);
    gemm_tf32<<<gFat, 256, 0, cx.s1>>>(g1, wg2r, gout, SQ, DMODEL, 128);
    cudaEventRecord(cx.evJ1, cx.s1);

    // ---- s0: all 4 fat projections in ONE batched launch ----
    Gemm4 g4;
    g4.A[0] = xr;  g4.B[0] = wqr; g4.C[0] = xq;
    g4.A[1] = xr;  g4.B[1] = wkr; g4.C[1] = xk;
    g4.A[2] = xr;  g4.B[2] = wvr; g4.C[2] = xv;
    g4.A[3] = ver; g4.B[3] = wvr; g4.C[3] = xve;
    gemm_tf32_b4<<<dim3(DMODEL / 128, SQ / 128, 4), 256>>>(g4, DMODEL, DMODEL);

    // ---- s2: conv-mix for v (needs xv, xve from batch) ----
    cudaEventRecord(cx.evJ2, 0);
    cudaStreamWaitEvent(cx.s2, cx.evJ2, 0);
    convmix_silu_kernel<<<EW, 256, 0, cx.s2>>>(xv, xve, wv_conv, lam, cv, nSD);
    cudaEventRecord(cx.evJ2, cx.s2);

    // ---- s0: fused conv+silu+l2norm for q/k (+ q·k dot) ----
    conv_l2_qk_kernel<<<SQ, 256>>>(xq, xk, wq_conv, wk_conv, cq, ck, qkd);

    // ---- join, then sequential tail ----
    cudaStreamWaitEvent(0, cx.evJ1, 0);
    cudaStreamWaitEvent(0, cx.evJ2, 0);

    kda_scan_kernel<<<NH * 16, 128>>>(cq, ck, cv, gpre, bpre, qkd, obuf);
    post_kernel<<<SQ, 256>>>(obuf, gout, bg2, w_norm);
    gemm_tf32<<<gFat, 256>>>(obuf, wor, out, SQ, DMODEL, DMODEL);
}